// round 10
// baseline (speedup 1.0000x reference)
#include <cuda_runtime.h>
#include <cuda_bf16.h>
#include <cstdint>

#define NROWS 131072
#define DIN   512
#define NH    512
#define DOUT  128
#define NBOUNDS 24

// ---------------- device scratch ---------------------------------------------
// activation digit planes (two ping-pong sets), [M][512] int8 row-major
__device__ __align__(256) int8_t g_qa1A[(size_t)NROWS * 512];
__device__ __align__(256) int8_t g_qa0A[(size_t)NROWS * 512];
__device__ __align__(256) int8_t g_qa1B[(size_t)NROWS * 512];
__device__ __align__(256) int8_t g_qa0B[(size_t)NROWS * 512];
// fp32 activation staging (one buffer, consumed by quant right after each layer)
__device__ __align__(256) float  g_act[(size_t)NROWS * 512];
__device__ __align__(256) float  g_srow[NROWS];
// weight digit planes, [N][K=512] int8, + per-col scales
__device__ __align__(256) int8_t g_wb1i[NH * DIN],  g_wb0i[NH * DIN];
__device__ __align__(256) int8_t g_wb1h[NH * NH],   g_wb0h[NH * NH];
__device__ __align__(256) int8_t g_wb1o[DOUT * NH], g_wb0o[DOUT * NH];
__device__ __align__(256) float  g_tin[NH], g_th[NH], g_tout[DOUT];
__device__ unsigned g_min_enc[DIN];
__device__ unsigned g_max_enc[DIN];

// ---------------- helpers ----------------------------------------------------
__device__ __forceinline__ uint32_t smem_u32(const void* p) {
    uint32_t a;
    asm("{ .reg .u64 t; cvta.to.shared.u64 t, %1; cvt.u32.u64 %0, t; }"
        : "=r"(a) : "l"(p));
    return a;
}
__device__ __forceinline__ void ldsm4(uint32_t* r, uint32_t a) {
    asm volatile("ldmatrix.sync.aligned.m8n8.x4.shared.b16 {%0,%1,%2,%3}, [%4];"
                 : "=r"(r[0]), "=r"(r[1]), "=r"(r[2]), "=r"(r[3]) : "r"(a));
}
// s8 MMA, s32 accumulate (exact)
__device__ __forceinline__ void mma16832(int* d, const uint32_t* a,
                                         uint32_t b0, uint32_t b1) {
    asm volatile(
        "mma.sync.aligned.m16n8k32.row.col.s32.s8.s8.s32 "
        "{%0,%1,%2,%3}, {%4,%5,%6,%7}, {%8,%9}, {%0,%1,%2,%3};"
        : "+r"(d[0]), "+r"(d[1]), "+r"(d[2]), "+r"(d[3])
        : "r"(a[0]), "r"(a[1]), "r"(a[2]), "r"(a[3]), "r"(b0), "r"(b1));
}
#define CP_ASYNC16(dst, src) \
    asm volatile("cp.async.cg.shared.global [%0], [%1], 16;" :: "r"(dst), "l"(src))
#define CP_COMMIT() asm volatile("cp.async.commit_group;" ::: "memory")
#define CP_WAIT2()  asm volatile("cp.async.wait_group 2;" ::: "memory")

// ---------------- min/max + discretize ---------------------------------------
__device__ __forceinline__ unsigned enc_f(float f) {
    unsigned u = __float_as_uint(f);
    return (u & 0x80000000u) ? ~u : (u | 0x80000000u);
}
__device__ __forceinline__ float dec_f(unsigned e) {
    unsigned u = (e & 0x80000000u) ? (e & 0x7FFFFFFFu) : ~e;
    return __uint_as_float(u);
}
__global__ void init_minmax() {
    int i = threadIdx.x;
    g_min_enc[i] = 0xFFFFFFFFu;
    g_max_enc[i] = 0x00000000u;
}
__global__ void colminmax(const float* __restrict__ x) {
    const int col = threadIdx.x;
    const size_t base = (size_t)blockIdx.x * 512 * DIN + col;
    float v0 = x[base];
    float mn = v0, mx = v0;
    for (int r = 1; r < 512; r++) {
        float v = x[base + (size_t)r * DIN];
        mn = fminf(mn, v);
        mx = fmaxf(mx, v);
    }
    atomicMin(&g_min_enc[col], enc_f(mn));
    atomicMax(&g_max_enc[col], enc_f(mx));
}
// writes exact small ints (0..24) into the set-A a0 digit plane
__global__ void discretize(const float* __restrict__ x) {
    const int col = threadIdx.x;
    const float bmin = dec_f(g_min_enc[col]);
    const float bmax = dec_f(g_max_enc[col]);
    const float range = __fsub_rn(bmax, bmin);
    float bounds[NBOUNDS];
#pragma unroll
    for (int k = 0; k < NBOUNDS; k++) {
        float frac = __fdiv_rn((float)(k + 1), 25.0f);
        bounds[k] = __fadd_rn(bmin, __fmul_rn(range, frac));
    }
    const size_t base = (size_t)blockIdx.x * 512 * DIN + col;
    for (int r = 0; r < 512; r++) {
        float v = x[base + (size_t)r * DIN];
        int idx = 0;
#pragma unroll
        for (int k = 0; k < NBOUNDS; k++) idx += (bounds[k] < v) ? 1 : 0;
        g_qa0A[base + (size_t)r * DIN] = (int8_t)idx;
    }
}

// ---------------- weight digitizer (warp per output col) ---------------------
// W is [K=512][N] fp32; produce b1,b0 planes [N][512] s8 and t[n].
__global__ void wprep8(const float* __restrict__ W, int8_t* __restrict__ b1,
                       int8_t* __restrict__ b0, float* __restrict__ tcol, int N) {
    const int n = blockIdx.x * 8 + (threadIdx.x >> 5);
    const int lane = threadIdx.x & 31;
    float w[16];
    float mx = 0.f;
#pragma unroll
    for (int i = 0; i < 16; i++) {
        w[i] = W[(size_t)(lane * 16 + i) * N + n];
        mx = fmaxf(mx, fabsf(w[i]));
    }
#pragma unroll
    for (int o = 16; o; o >>= 1) mx = fmaxf(mx, __shfl_xor_sync(~0u, mx, o));
    const float inv = mx > 0.f ? 16256.f / mx : 0.f;
    if (lane == 0) tcol[n] = mx * (1.f / 16256.f);
    int8_t c1[16], c0[16];
#pragma unroll
    for (int i = 0; i < 16; i++) {
        int q = __float2int_rn(w[i] * inv);
        int hi = (q + 64) >> 7;                 // round-half-up digit
        c1[i] = (int8_t)hi;
        c0[i] = (int8_t)(q - (hi << 7));        // in [-64, 63]
    }
    size_t off = (size_t)n * 512 + lane * 16;
    *reinterpret_cast<int4*>(b1 + off) = *reinterpret_cast<int4*>(c1);
    *reinterpret_cast<int4*>(b0 + off) = *reinterpret_cast<int4*>(c0);
}

// ---------------- activation quantizer (warp per row) ------------------------
__global__ void quant(const float* __restrict__ act, int8_t* __restrict__ q1,
                      int8_t* __restrict__ q0, float* __restrict__ srow) {
    const int row = blockIdx.x * 8 + (threadIdx.x >> 5);
    const int lane = threadIdx.x & 31;
    const float* p = act + (size_t)row * 512 + lane * 16;
    float4 v[4];
    float mx = 0.f;
#pragma unroll
    for (int i = 0; i < 4; i++) {
        v[i] = *reinterpret_cast<const float4*>(p + i * 4);
        mx = fmaxf(mx, fmaxf(fmaxf(v[i].x, v[i].y), fmaxf(v[i].z, v[i].w)));
    }
#pragma unroll
    for (int o = 16; o; o >>= 1) mx = fmaxf(mx, __shfl_xor_sync(~0u, mx, o));
    const float inv = mx > 0.f ? 16256.f / mx : 0.f;
    if (lane == 0) srow[row] = mx * (1.f / 16256.f);
    const float* vf = reinterpret_cast<const float*>(v);
    int8_t c1[16], c0[16];
#pragma unroll
    for (int i = 0; i < 16; i++) {
        int q = __float2int_rn(vf[i] * inv);    // q in [0, 16256] (relu'd input)
        int hi = (q + 64) >> 7;
        c1[i] = (int8_t)hi;
        c0[i] = (int8_t)(q - (hi << 7));
    }
    size_t off = (size_t)row * 512 + lane * 16;
    *reinterpret_cast<int4*>(q1 + off) = *reinterpret_cast<int4*>(c1);
    *reinterpret_cast<int4*>(q0 + off) = *reinterpret_cast<int4*>(c0);
}

// ---------------- int8 two-digit GEMM (mma.sync s8, s32 accum) ---------------
// BM=64, BN=128, 256 threads (2m x 4n warps, warp tile 32x32).
// Digit planes [row][512B]; K consumed in 8 half-stages of 64B across 2 buffers.
// hidden: out = s_row*t_col*(16384*D11 + 128*(a1b0+a0b1)) + bias  (a0b0 dropped)
// L1 (AEXACT, a0 only, s=1): out = t_col*(128*Dh + Dl) + bias      (exact)
#define BUFSZ 49152
#define SM_A1 0
#define SM_A0 8192
#define SM_B1 16384
#define SM_B0 32768

template <int AEXACT, int FINAL>
__global__ __launch_bounds__(256, 2)
void mlp_gemm8(const int8_t* __restrict__ A1, const int8_t* __restrict__ A0,
               const int8_t* __restrict__ B1, const int8_t* __restrict__ B0,
               const float* __restrict__ tcol, const float* __restrict__ srow,
               const float* __restrict__ bias, float* __restrict__ Out) {
    extern __shared__ __align__(1024) unsigned char sm[];
    const uint32_t smb = smem_u32(sm);
    const int tid = threadIdx.x;
    const int lane = tid & 31, wid = tid >> 5;
    const int wm = wid >> 2, wn = wid & 3;      // 2 x 4 warp grid
    const int m0 = blockIdx.y * 64;
    const int n0 = blockIdx.x * 128;

    int chi[2][4][4], clo[2][4][4];             // HI bank / MID(or LO) bank
#pragma unroll
    for (int i = 0; i < 2; i++)
#pragma unroll
        for (int j = 0; j < 4; j++)
#pragma unroll
            for (int q = 0; q < 4; q++) { chi[i][j][q] = 0; clo[i][j][q] = 0; }

    // ---- half-stage loader: 64B k-slab into half (ch&1) of buffer ----------
    const int lr4 = tid >> 2, lc4 = tid & 3;
    auto load_half = [&](int ch) {
        const uint32_t sb = smb + (uint32_t)((ch >> 1) & 1) * BUFSZ;
        const int h4 = (ch & 1) * 4;
        const int kb = ch * 64;                 // byte offset within 512B row
        {   // A planes: 64 rows x 4 slots
            int r = lr4;                        // 0..63
            uint32_t slot = (uint32_t)((h4 + lc4) ^ (r & 7)) << 4;
            if (!AEXACT)
                CP_ASYNC16(sb + SM_A1 + r * 128 + slot,
                           A1 + (size_t)(m0 + r) * 512 + kb + lc4 * 16);
            CP_ASYNC16(sb + SM_A0 + r * 128 + slot,
                       A0 + (size_t)(m0 + r) * 512 + kb + lc4 * 16);
        }
#pragma unroll
        for (int it = 0; it < 2; it++) {        // B planes: 128 rows x 4 slots
            int r = lr4 + it * 64;
            uint32_t slot = (uint32_t)((h4 + lc4) ^ (r & 7)) << 4;
            CP_ASYNC16(sb + SM_B1 + r * 128 + slot,
                       B1 + (size_t)(n0 + r) * 512 + kb + lc4 * 16);
            CP_ASYNC16(sb + SM_B0 + r * 128 + slot,
                       B0 + (size_t)(n0 + r) * 512 + kb + lc4 * 16);
        }
    };

    const int arow = lane & 15;
    const int kbl  = lane >> 4;                 // 16B-slot selector (k-half)

    uint32_t aoff[2], boff[2];
    int amod[2], bmod[2];
#pragma unroll
    for (int mf = 0; mf < 2; mf++) {
        int r = wm * 32 + mf * 16 + arow;       // 0..63
        aoff[mf] = r * 128; amod[mf] = r & 7;
    }
#pragma unroll
    for (int g = 0; g < 2; g++) {
        int r = wn * 32 + g * 16 + arow;        // 0..127
        boff[g] = r * 128; bmod[g] = r & 7;
    }

    load_half(0); CP_COMMIT();
    load_half(1); CP_COMMIT();
    load_half(2); CP_COMMIT();

#pragma unroll 1
    for (int ch = 0; ch < 8; ch++) {
        CP_WAIT2();
        __syncthreads();
        if (ch + 3 < 8) load_half(ch + 3);
        CP_COMMIT();

        const uint32_t sb = smb + (uint32_t)((ch >> 1) & 1) * BUFSZ;
        const int h4 = (ch & 1) * 4;
#pragma unroll
        for (int kk = 0; kk < 2; kk++) {
            const int c = h4 + kk * 2 + kbl;
            uint32_t a1f[2][4], a0f[2][4], b1f[2][4], b0f[2][4];
#pragma unroll
            for (int mf = 0; mf < 2; mf++) {
                uint32_t o = aoff[mf] + (uint32_t)((c ^ amod[mf]) << 4);
                if (!AEXACT) ldsm4(a1f[mf], sb + SM_A1 + o);
                ldsm4(a0f[mf], sb + SM_A0 + o);
            }
#pragma unroll
            for (int g = 0; g < 2; g++) {
                uint32_t o = boff[g] + (uint32_t)((c ^ bmod[g]) << 4);
                ldsm4(b1f[g], sb + SM_B1 + o);
                ldsm4(b0f[g], sb + SM_B0 + o);
            }
#pragma unroll
            for (int g = 0; g < 2; g++)
#pragma unroll
                for (int mf = 0; mf < 2; mf++) {
                    if (AEXACT) {
                        // Dh = a0*b1, Dl = a0*b0 (exact)
                        mma16832(chi[mf][2 * g],     a0f[mf], b1f[g][0], b1f[g][2]);
                        mma16832(chi[mf][2 * g + 1], a0f[mf], b1f[g][1], b1f[g][3]);
                        mma16832(clo[mf][2 * g],     a0f[mf], b0f[g][0], b0f[g][2]);
                        mma16832(clo[mf][2 * g + 1], a0f[mf], b0f[g][1], b0f[g][3]);
                    } else {
                        // D11 = a1*b1; Dm = a1*b0 + a0*b1 (shared bank)
                        mma16832(chi[mf][2 * g],     a1f[mf], b1f[g][0], b1f[g][2]);
                        mma16832(chi[mf][2 * g + 1], a1f[mf], b1f[g][1], b1f[g][3]);
                        mma16832(clo[mf][2 * g],     a1f[mf], b0f[g][0], b0f[g][2]);
                        mma16832(clo[mf][2 * g + 1], a1f[mf], b0f[g][1], b0f[g][3]);
                        mma16832(clo[mf][2 * g],     a0f[mf], b1f[g][0], b1f[g][2]);
                        mma16832(clo[mf][2 * g + 1], a0f[mf], b1f[g][1], b1f[g][3]);
                    }
                }
        }
    }

    // ---- epilogue: combine digits, scale, bias, relu, store fp32 -----------
    constexpr float SH = AEXACT ? 128.f : 16384.f;
    constexpr float SL = AEXACT ? 1.f   : 128.f;
    const int OW = FINAL ? DOUT : 512;
    const int qr = lane >> 2, qc = lane & 3;
#pragma unroll
    for (int mf = 0; mf < 2; mf++) {
        const int r0 = m0 + wm * 32 + mf * 16 + qr;
        const float s0 = AEXACT ? 1.f : srow[r0];
        const float s1 = AEXACT ? 1.f : srow[r0 + 8];
#pragma unroll
        for (int nf = 0; nf < 4; nf++) {
            const int n = n0 + wn * 32 + nf * 8 + qc * 2;
            const float t0 = tcol[n], t1 = tcol[n + 1];
            const float bv0 = bias[n], bv1 = bias[n + 1];
            const int* h = chi[mf][nf];
            const int* l = clo[mf][nf];
            float v00 = fmaxf(((float)h[0] * SH + (float)l[0] * SL) * (s0 * t0) + bv0, 0.f);
            float v01 = fmaxf(((float)h[1] * SH + (float)l[1] * SL) * (s0 * t1) + bv1, 0.f);
            float v10 = fmaxf(((float)h[2] * SH + (float)l[2] * SL) * (s1 * t0) + bv0, 0.f);
            float v11 = fmaxf(((float)h[3] * SH + (float)l[3] * SL) * (s1 * t1) + bv1, 0.f);
            *reinterpret_cast<float2*>(Out + (size_t)r0 * OW + n) = make_float2(v00, v01);
            *reinterpret_cast<float2*>(Out + (size_t)(r0 + 8) * OW + n) = make_float2(v10, v11);
        }
    }
}

// ---------------- tail zero --------------------------------------------------
__global__ void zero_tail(float* out, size_t start, size_t count) {
    size_t i = (size_t)blockIdx.x * blockDim.x + threadIdx.x;
    if (i < count) out[start + i] = 0.0f;
}

// ---------------- launch -----------------------------------------------------
extern "C" void kernel_launch(void* const* d_in, const int* in_sizes, int n_in,
                              void* d_out, int out_size) {
    const float* x     = (const float*)d_in[0];
    const float* W_in  = (const float*)d_in[1];
    const float* b_in  = (const float*)d_in[2];
    const float* W_h   = (const float*)d_in[3];
    const float* b_h   = (const float*)d_in[4];
    const float* W_out = (const float*)d_in[5];
    const float* b_out = (const float*)d_in[6];
    float* out = (float*)d_out;

    int8_t *qa1A, *qa0A, *qa1B, *qa0B, *wb1i, *wb0i, *wb1h, *wb0h, *wb1o, *wb0o;
    float *act, *srow, *tin, *th, *tout;
    cudaGetSymbolAddress((void**)&qa1A, g_qa1A);
    cudaGetSymbolAddress((void**)&qa0A, g_qa0A);
    cudaGetSymbolAddress((void**)&qa1B, g_qa1B);
    cudaGetSymbolAddress((void**)&qa0B, g_qa0B);
    cudaGetSymbolAddress((void**)&wb1i, g_wb1i);
    cudaGetSymbolAddress((void**)&wb0i, g_wb0i);
    cudaGetSymbolAddress((void**)&wb1h, g_wb1h);
    cudaGetSymbolAddress((void**)&wb0h, g_wb0h);
    cudaGetSymbolAddress((void**)&wb1o, g_wb1o);
    cudaGetSymbolAddress((void**)&wb0o, g_wb0o);
    cudaGetSymbolAddress((void**)&act,  g_act);
    cudaGetSymbolAddress((void**)&srow, g_srow);
    cudaGetSymbolAddress((void**)&tin,  g_tin);
    cudaGetSymbolAddress((void**)&th,   g_th);
    cudaGetSymbolAddress((void**)&tout, g_tout);

    const size_t smem = 2 * BUFSZ;  // 96KB per CTA -> 2 CTAs/SM
    cudaFuncSetAttribute(mlp_gemm8<1, 0>, cudaFuncAttributeMaxDynamicSharedMemorySize, smem);
    cudaFuncSetAttribute(mlp_gemm8<0, 0>, cudaFuncAttributeMaxDynamicSharedMemorySize, smem);
    cudaFuncSetAttribute(mlp_gemm8<0, 1>, cudaFuncAttributeMaxDynamicSharedMemorySize, smem);

    init_minmax<<<1, DIN>>>();
    colminmax<<<NROWS / 512, DIN>>>(x);
    discretize<<<NROWS / 512, DIN>>>(x);     // -> qa0A (exact ints)

    wprep8<<<NH / 8, 256>>>(W_in, wb1i, wb0i, tin, NH);
    wprep8<<<NH / 8, 256>>>(W_h, wb1h, wb0h, th, NH);
    wprep8<<<DOUT / 8, 256>>>(W_out, wb1o, wb0o, tout, DOUT);

    dim3 blk(256);
    dim3 gh(4, NROWS / 64);    // hidden: N=512
    dim3 gf(1, NROWS / 64);    // final:  N=128
    dim3 qg(NROWS / 8);

    // L1 (exact single-digit A) -> act
    mlp_gemm8<1, 0><<<gh, blk, smem>>>(nullptr, qa0A, wb1i, wb0i, tin, nullptr, b_in, act);
    // L2..L6: quantize prev act, then two-digit GEMM
    quant<<<qg, 256>>>(act, qa1B, qa0B, srow);
    mlp_gemm8<0, 0><<<gh, blk, smem>>>(qa1B, qa0B, wb1h, wb0h, th, srow, b_h, act);
    quant<<<qg, 256>>>(act, qa1A, qa0A, srow);
    mlp_gemm8<0, 0><<<gh, blk, smem>>>(qa1A, qa0A, wb1h, wb0h, th, srow, b_h, act);
    quant<<<qg, 256>>>(act, qa1B, qa0B, srow);
    mlp_gemm8<0, 0><<<gh, blk, smem>>>(qa1B, qa0B, wb1h, wb0h, th, srow, b_h, act);
    quant<<<qg, 256>>>(act, qa1A, qa0A, srow);
    mlp_gemm8<0, 0><<<gh, blk, smem>>>(qa1A, qa0A, wb1h, wb0h, th, srow, b_h, act);
    quant<<<qg, 256>>>(act, qa1B, qa0B, srow);
    mlp_gemm8<0, 0><<<gh, blk, smem>>>(qa1B, qa0B, wb1h, wb0h, th, srow, b_h, act);
    // L7: final
    quant<<<qg, 256>>>(act, qa1A, qa0A, srow);
    mlp_gemm8<0, 1><<<gf, blk, smem>>>(qa1A, qa0A, wb1o, wb0o, tout, srow, b_out, out);

    size_t y_elems = (size_t)NROWS * DOUT;
    if ((size_t)out_size > y_elems) {
        size_t cnt = (size_t)out_size - y_elems;
        zero_tail<<<(unsigned)((cnt + 255) / 256), 256>>>(out, y_elems, cnt);
    }
}

// round 12
// speedup vs baseline: 2.9173x; 2.9173x over previous
#include <cuda_runtime.h>
#include <cuda_fp16.h>
#include <cstdint>

#define NROWS 131072
#define DIN   512
#define NH    512
#define DOUT  128
#define NBOUNDS 24

// ---------------- device scratch ---------------------------------------------
// activations: single fp16 plane, ping-pong; [M][512] row-major
__device__ __align__(256) __half g_actA[(size_t)NROWS * 512];
__device__ __align__(256) __half g_actB[(size_t)NROWS * 512];
// weights transposed [N][K]: hi plane + lo plane scaled by 2^11
__device__ __align__(256) __half g_wih[NH * DIN],  g_wil[NH * DIN];
__device__ __align__(256) __half g_whh[NH * NH],   g_whl[NH * NH];
__device__ __align__(256) __half g_woh[DOUT * NH], g_wol[DOUT * NH];
__device__ unsigned g_min_enc[DIN];
__device__ unsigned g_max_enc[DIN];

// ---------------- helpers ----------------------------------------------------
__device__ __forceinline__ uint32_t smem_u32(const void* p) {
    uint32_t a;
    asm("{ .reg .u64 t; cvta.to.shared.u64 t, %1; cvt.u32.u64 %0, t; }"
        : "=r"(a) : "l"(p));
    return a;
}
__device__ __forceinline__ void ldsm4(uint32_t* r, uint32_t a) {
    asm volatile("ldmatrix.sync.aligned.m8n8.x4.shared.b16 {%0,%1,%2,%3}, [%4];"
                 : "=r"(r[0]), "=r"(r[1]), "=r"(r[2]), "=r"(r[3]) : "r"(a));
}
__device__ __forceinline__ void mma16816h(float* d, const uint32_t* a,
                                          uint32_t b0, uint32_t b1) {
    asm volatile(
        "mma.sync.aligned.m16n8k16.row.col.f32.f16.f16.f32 "
        "{%0,%1,%2,%3}, {%4,%5,%6,%7}, {%8,%9}, {%0,%1,%2,%3};"
        : "+f"(d[0]), "+f"(d[1]), "+f"(d[2]), "+f"(d[3])
        : "r"(a[0]), "r"(a[1]), "r"(a[2]), "r"(a[3]), "r"(b0), "r"(b1));
}
#define CP_ASYNC16(dst, src) \
    asm volatile("cp.async.cg.shared.global [%0], [%1], 16;" :: "r"(dst), "l"(src))
#define CP_COMMIT() asm volatile("cp.async.commit_group;" ::: "memory")
#define CP_WAIT2()  asm volatile("cp.async.wait_group 2;" ::: "memory")

// ---------------- min/max + discretize ---------------------------------------
__device__ __forceinline__ unsigned enc_f(float f) {
    unsigned u = __float_as_uint(f);
    return (u & 0x80000000u) ? ~u : (u | 0x80000000u);
}
__device__ __forceinline__ float dec_f(unsigned e) {
    unsigned u = (e & 0x80000000u) ? (e & 0x7FFFFFFFu) : ~e;
    return __uint_as_float(u);
}
__global__ void init_minmax() {
    int i = threadIdx.x;
    g_min_enc[i] = 0xFFFFFFFFu;
    g_max_enc[i] = 0x00000000u;
}
__global__ void colminmax(const float* __restrict__ x) {
    const int col = threadIdx.x;
    const size_t base = (size_t)blockIdx.x * 512 * DIN + col;
    float v0 = x[base];
    float mn = v0, mx = v0;
    for (int r = 1; r < 512; r++) {
        float v = x[base + (size_t)r * DIN];
        mn = fminf(mn, v);
        mx = fmaxf(mx, v);
    }
    atomicMin(&g_min_enc[col], enc_f(mn));
    atomicMax(&g_max_enc[col], enc_f(mx));
}
// writes exact small ints (0..24, exact in fp16) into actA
__global__ void discretize(const float* __restrict__ x) {
    const int col = threadIdx.x;
    const float bmin = dec_f(g_min_enc[col]);
    const float bmax = dec_f(g_max_enc[col]);
    const float range = __fsub_rn(bmax, bmin);
    float bounds[NBOUNDS];
#pragma unroll
    for (int k = 0; k < NBOUNDS; k++) {
        float frac = __fdiv_rn((float)(k + 1), 25.0f);
        bounds[k] = __fadd_rn(bmin, __fmul_rn(range, frac));
    }
    const size_t base = (size_t)blockIdx.x * 512 * DIN + col;
    for (int r = 0; r < 512; r++) {
        float v = x[base + (size_t)r * DIN];
        int idx = 0;
#pragma unroll
        for (int k = 0; k < NBOUNDS; k++) idx += (bounds[k] < v) ? 1 : 0;
        g_actA[base + (size_t)r * DIN] = __float2half_rn((float)idx);
    }
}

// ---------------- weight split + transpose (fp16 hi + scaled lo) -------------
// w = h + l/2048, l stored as fp16 of (w-h)*2048 (keeps lo plane normal-range)
__global__ void wprep(const float* __restrict__ W, __half* __restrict__ hi,
                      __half* __restrict__ lo, int N, int K) {
    int i = blockIdx.x * blockDim.x + threadIdx.x;
    if (i >= N * K) return;
    int k = i / N, n = i % N;  // W is [K][N]
    float w = W[i];
    __half h = __float2half_rn(w);
    __half l = __float2half_rn((w - __half2float(h)) * 2048.0f);
    hi[(size_t)n * K + k] = h;  // transposed [N][K]
    lo[(size_t)n * K + k] = l;
}

// ---------------- fp16 2-term GEMM (mma.sync HMMA, dual accum banks) ---------
// C = relu(A@(Wh + Wl/2048) + bias); A fp16 [M][512], W planes [N][512].
// BM=64, BN=128, 256 threads (2m x 4n warps, warp tile 32x32).
// 2 buffers x BK=64, consumed in BK=32 halves -> 4 half-stage pipeline.
// 80KB/CTA -> 2 CTAs/SM.
#define BUFSZ 40960
#define SM_A  0
#define SM_BH 8192
#define SM_BL 24576

template <int FINAL>
__global__ __launch_bounds__(256, 2)
void mlp_gemm(const __half* __restrict__ A, const __half* __restrict__ Bh,
              const __half* __restrict__ Bl, const float* __restrict__ bias,
              __half* __restrict__ Oh, float* __restrict__ Of32) {
    extern __shared__ __align__(1024) unsigned char sm[];
    const uint32_t smb = smem_u32(sm);
    const int tid = threadIdx.x;
    const int lane = tid & 31, wid = tid >> 5;
    const int wm = wid >> 2, wn = wid & 3;      // 2 x 4 warp grid
    const int m0 = blockIdx.y * 64;
    const int n0 = blockIdx.x * 128;

    float ahi[2][4][4], alo[2][4][4];           // hi-term / scaled-lo-term banks
#pragma unroll
    for (int i = 0; i < 2; i++)
#pragma unroll
        for (int j = 0; j < 4; j++)
#pragma unroll
            for (int q = 0; q < 4; q++) { ahi[i][j][q] = 0.f; alo[i][j][q] = 0.f; }

    // ---- half-stage loader: BK=32 slab (64B per row) into half (ch&1) ------
    const int lr4 = tid >> 2, lc4 = tid & 3;
    auto load_half = [&](int ch) {
        const uint32_t sb = smb + (uint32_t)((ch >> 1) & 1) * BUFSZ;
        const int h4 = (ch & 1) * 4;
        const int k0 = ch * 32;
        {   // A plane: 64 rows x 4 slots
            int r = lr4;
            uint32_t slot = (uint32_t)((h4 + lc4) ^ (r & 7)) << 4;
            CP_ASYNC16(sb + SM_A + r * 128 + slot,
                       A + (size_t)(m0 + r) * 512 + k0 + lc4 * 8);
        }
#pragma unroll
        for (int it = 0; it < 2; it++) {        // B planes: 128 rows x 4 slots
            int r = lr4 + it * 64;
            uint32_t slot = (uint32_t)((h4 + lc4) ^ (r & 7)) << 4;
            CP_ASYNC16(sb + SM_BH + r * 128 + slot,
                       Bh + (size_t)(n0 + r) * 512 + k0 + lc4 * 8);
            CP_ASYNC16(sb + SM_BL + r * 128 + slot,
                       Bl + (size_t)(n0 + r) * 512 + k0 + lc4 * 8);
        }
    };

    const int arow = lane & 15;
    const int kbl  = lane >> 4;

    uint32_t aoff[2], boff[2];
    int amod[2], bmod[2];
#pragma unroll
    for (int mf = 0; mf < 2; mf++) {
        int r = wm * 32 + mf * 16 + arow;       // 0..63
        aoff[mf] = r * 128; amod[mf] = r & 7;
    }
#pragma unroll
    for (int g = 0; g < 2; g++) {
        int r = wn * 32 + g * 16 + arow;        // 0..127
        boff[g] = r * 128; bmod[g] = r & 7;
    }

    load_half(0); CP_COMMIT();
    load_half(1); CP_COMMIT();
    load_half(2); CP_COMMIT();

#pragma unroll 1
    for (int ch = 0; ch < 16; ch++) {
        CP_WAIT2();
        __syncthreads();
        if (ch + 3 < 16) load_half(ch + 3);
        CP_COMMIT();

        const uint32_t sb = smb + (uint32_t)((ch >> 1) & 1) * BUFSZ;
        const int h4 = (ch & 1) * 4;
#pragma unroll
        for (int kk = 0; kk < 2; kk++) {
            const int c = h4 + kk * 2 + kbl;
            uint32_t af[2][4], bh[2][4], bl[2][4];
#pragma unroll
            for (int mf = 0; mf < 2; mf++) {
                uint32_t o = aoff[mf] + (uint32_t)((c ^ amod[mf]) << 4);
                ldsm4(af[mf], sb + SM_A + o);
            }
#pragma unroll
            for (int g = 0; g < 2; g++) {
                uint32_t o = boff[g] + (uint32_t)((c ^ bmod[g]) << 4);
                ldsm4(bh[g], sb + SM_BH + o);
                ldsm4(bl[g], sb + SM_BL + o);
            }
#pragma unroll
            for (int g = 0; g < 2; g++)
#pragma unroll
                for (int mf = 0; mf < 2; mf++) {
                    mma16816h(ahi[mf][2 * g],     af[mf], bh[g][0], bh[g][2]);
                    mma16816h(ahi[mf][2 * g + 1], af[mf], bh[g][1], bh[g][3]);
                    mma16816h(alo[mf][2 * g],     af[mf], bl[g][0], bl[g][2]);
                    mma16816h(alo[mf][2 * g + 1], af[mf], bl[g][1], bl[g][3]);
                }
        }
    }

    // ---- epilogue: combine banks, bias, relu, store -------------------------
    constexpr float INV = 1.0f / 2048.0f;
    const int OW = FINAL ? DOUT : 512;
    const int qr = lane >> 2, qc = lane & 3;
#pragma unroll
    for (int mf = 0; mf < 2; mf++) {
        const int r0 = m0 + wm * 32 + mf * 16 + qr;
#pragma unroll
        for (int nf = 0; nf < 4; nf++) {
            const int n = n0 + wn * 32 + nf * 8 + qc * 2;
            const float bv0 = bias[n], bv1 = bias[n + 1];
            const float* h = ahi[mf][nf];
            const float* l = alo[mf][nf];
            float v00 = fmaxf(h[0] + l[0] * INV + bv0, 0.f);
            float v01 = fmaxf(h[1] + l[1] * INV + bv1, 0.f);
            float v10 = fmaxf(h[2] + l[2] * INV + bv0, 0.f);
            float v11 = fmaxf(h[3] + l[3] * INV + bv1, 0.f);
            if (FINAL) {
                *reinterpret_cast<float2*>(Of32 + (size_t)r0 * OW + n) =
                    make_float2(v00, v01);
                *reinterpret_cast<float2*>(Of32 + (size_t)(r0 + 8) * OW + n) =
                    make_float2(v10, v11);
            } else {
                __half h00 = __float2half_rn(v00), h01 = __float2half_rn(v01);
                __half h10 = __float2half_rn(v10), h11 = __float2half_rn(v11);
                uint32_t p0 = (uint32_t)*reinterpret_cast<unsigned short*>(&h00) |
                              ((uint32_t)*reinterpret_cast<unsigned short*>(&h01) << 16);
                uint32_t p1 = (uint32_t)*reinterpret_cast<unsigned short*>(&h10) |
                              ((uint32_t)*reinterpret_cast<unsigned short*>(&h11) << 16);
                *reinterpret_cast<uint32_t*>(Oh + (size_t)r0 * 512 + n) = p0;
                *reinterpret_cast<uint32_t*>(Oh + (size_t)(r0 + 8) * 512 + n) = p1;
            }
        }
    }
}

// ---------------- tail zero --------------------------------------------------
__global__ void zero_tail(float* out, size_t start, size_t count) {
    size_t i = (size_t)blockIdx.x * blockDim.x + threadIdx.x;
    if (i < count) out[start + i] = 0.0f;
}

// ---------------- launch -----------------------------------------------------
extern "C" void kernel_launch(void* const* d_in, const int* in_sizes, int n_in,
                              void* d_out, int out_size) {
    const float* x     = (const float*)d_in[0];
    const float* W_in  = (const float*)d_in[1];
    const float* b_in  = (const float*)d_in[2];
    const float* W_h   = (const float*)d_in[3];
    const float* b_h   = (const float*)d_in[4];
    const float* W_out = (const float*)d_in[5];
    const float* b_out = (const float*)d_in[6];
    float* out = (float*)d_out;

    __half *actA, *actB, *wih, *wil, *whh, *whl, *woh, *wol;
    cudaGetSymbolAddress((void**)&actA, g_actA);
    cudaGetSymbolAddress((void**)&actB, g_actB);
    cudaGetSymbolAddress((void**)&wih, g_wih);
    cudaGetSymbolAddress((void**)&wil, g_wil);
    cudaGetSymbolAddress((void**)&whh, g_whh);
    cudaGetSymbolAddress((void**)&whl, g_whl);
    cudaGetSymbolAddress((void**)&woh, g_woh);
    cudaGetSymbolAddress((void**)&wol, g_wol);

    const size_t smem = 2 * BUFSZ;  // 80KB per CTA -> 2 CTAs/SM
    cudaFuncSetAttribute(mlp_gemm<0>, cudaFuncAttributeMaxDynamicSharedMemorySize, smem);
    cudaFuncSetAttribute(mlp_gemm<1>, cudaFuncAttributeMaxDynamicSharedMemorySize, smem);

    init_minmax<<<1, DIN>>>();
    colminmax<<<NROWS / 512, DIN>>>(x);
    discretize<<<NROWS / 512, DIN>>>(x);     // -> actA (exact ints in fp16)

    wprep<<<(DIN * NH + 255) / 256, 256>>>(W_in, wih, wil, NH, DIN);
    wprep<<<(NH * NH + 255) / 256, 256>>>(W_h, whh, whl, NH, NH);
    wprep<<<(NH * DOUT + 255) / 256, 256>>>(W_out, woh, wol, DOUT, NH);

    dim3 blk(256);
    dim3 gh(4, NROWS / 64);    // hidden: N=512
    dim3 gf(1, NROWS / 64);    // final:  N=128

    // L1 (exact input)
    mlp_gemm<0><<<gh, blk, smem>>>(actA, wih, wil, b_in, actB, nullptr);
    // L2..L6: shared W_h, ping-pong
    mlp_gemm<0><<<gh, blk, smem>>>(actB, whh, whl, b_h, actA, nullptr);
    mlp_gemm<0><<<gh, blk, smem>>>(actA, whh, whl, b_h, actB, nullptr);
    mlp_gemm<0><<<gh, blk, smem>>>(actB, whh, whl, b_h, actA, nullptr);
    mlp_gemm<0><<<gh, blk, smem>>>(actA, whh, whl, b_h, actB, nullptr);
    mlp_gemm<0><<<gh, blk, smem>>>(actB, whh, whl, b_h, actA, nullptr);
    // L7: final, fp32 out
    mlp_gemm<1><<<gf, blk, smem>>>(actA, woh, wol, b_out, nullptr, out);

    size_t y_elems = (size_t)NROWS * DOUT;
    if ((size_t)out_size > y_elems) {
        size_t cnt = (size_t)out_size - y_elems;
        zero_tail<<<(unsigned)((cnt + 255) / 256), 256>>>(out, y_elems, cnt);
    }
}

// round 13
// speedup vs baseline: 4.8082x; 1.6482x over previous
#include <cuda_runtime.h>
#include <cuda_fp16.h>
#include <cstdint>

#define NROWS 131072
#define DIN   512
#define NH    512
#define DOUT  128
#define NBOUNDS 24

// ---------------- device scratch ---------------------------------------------
// activations: single fp16 plane, ping-pong; [M][512] row-major
__device__ __align__(256) __half g_actA[(size_t)NROWS * 512];
__device__ __align__(256) __half g_actB[(size_t)NROWS * 512];
// weights transposed [N][K], single fp16 plane
__device__ __align__(256) __half g_wi[NH * DIN];
__device__ __align__(256) __half g_wh[NH * NH];
__device__ __align__(256) __half g_wo[DOUT * NH];
__device__ unsigned g_min_enc[DIN];
__device__ unsigned g_max_enc[DIN];

// ---------------- helpers ----------------------------------------------------
__device__ __forceinline__ uint32_t smem_u32(const void* p) {
    uint32_t a;
    asm("{ .reg .u64 t; cvta.to.shared.u64 t, %1; cvt.u32.u64 %0, t; }"
        : "=r"(a) : "l"(p));
    return a;
}
__device__ __forceinline__ void ldsm4(uint32_t* r, uint32_t a) {
    asm volatile("ldmatrix.sync.aligned.m8n8.x4.shared.b16 {%0,%1,%2,%3}, [%4];"
                 : "=r"(r[0]), "=r"(r[1]), "=r"(r[2]), "=r"(r[3]) : "r"(a));
}
__device__ __forceinline__ void mma16816h(float* d, const uint32_t* a,
                                          uint32_t b0, uint32_t b1) {
    asm volatile(
        "mma.sync.aligned.m16n8k16.row.col.f32.f16.f16.f32 "
        "{%0,%1,%2,%3}, {%4,%5,%6,%7}, {%8,%9}, {%0,%1,%2,%3};"
        : "+f"(d[0]), "+f"(d[1]), "+f"(d[2]), "+f"(d[3])
        : "r"(a[0]), "r"(a[1]), "r"(a[2]), "r"(a[3]), "r"(b0), "r"(b1));
}
#define CP_ASYNC16(dst, src) \
    asm volatile("cp.async.cg.shared.global [%0], [%1], 16;" :: "r"(dst), "l"(src))
#define CP_COMMIT() asm volatile("cp.async.commit_group;" ::: "memory")
#define CP_WAIT2()  asm volatile("cp.async.wait_group 2;" ::: "memory")

// ---------------- min/max + discretize ---------------------------------------
__device__ __forceinline__ unsigned enc_f(float f) {
    unsigned u = __float_as_uint(f);
    return (u & 0x80000000u) ? ~u : (u | 0x80000000u);
}
__device__ __forceinline__ float dec_f(unsigned e) {
    unsigned u = (e & 0x80000000u) ? (e & 0x7FFFFFFFu) : ~e;
    return __uint_as_float(u);
}
__global__ void init_minmax() {
    int i = threadIdx.x;
    g_min_enc[i] = 0xFFFFFFFFu;
    g_max_enc[i] = 0x00000000u;
}
__global__ void colminmax(const float* __restrict__ x) {
    const int col = threadIdx.x;
    const size_t base = (size_t)blockIdx.x * 512 * DIN + col;
    float v0 = x[base];
    float mn = v0, mx = v0;
    for (int r = 1; r < 512; r++) {
        float v = x[base + (size_t)r * DIN];
        mn = fminf(mn, v);
        mx = fmaxf(mx, v);
    }
    atomicMin(&g_min_enc[col], enc_f(mn));
    atomicMax(&g_max_enc[col], enc_f(mx));
}
// writes exact small ints (0..24, exact in fp16) into actA
__global__ void discretize(const float* __restrict__ x) {
    const int col = threadIdx.x;
    const float bmin = dec_f(g_min_enc[col]);
    const float bmax = dec_f(g_max_enc[col]);
    const float range = __fsub_rn(bmax, bmin);
    float bounds[NBOUNDS];
#pragma unroll
    for (int k = 0; k < NBOUNDS; k++) {
        float frac = __fdiv_rn((float)(k + 1), 25.0f);
        bounds[k] = __fadd_rn(bmin, __fmul_rn(range, frac));
    }
    const size_t base = (size_t)blockIdx.x * 512 * DIN + col;
    for (int r = 0; r < 512; r++) {
        float v = x[base + (size_t)r * DIN];
        int idx = 0;
#pragma unroll
        for (int k = 0; k < NBOUNDS; k++) idx += (bounds[k] < v) ? 1 : 0;
        g_actA[base + (size_t)r * DIN] = __float2half_rn((float)idx);
    }
}

// ---------------- weight convert + transpose (single fp16 plane) -------------
__global__ void wprep(const float* __restrict__ W, __half* __restrict__ hi,
                      int N, int K) {
    int i = blockIdx.x * blockDim.x + threadIdx.x;
    if (i >= N * K) return;
    int k = i / N, n = i % N;  // W is [K][N]
    hi[(size_t)n * K + k] = __float2half_rn(W[i]);  // transposed [N][K]
}

// ---------------- fp16 GEMM (mma.sync HMMA, fp32 accum) ----------------------
// C = relu(A@W + bias); A fp16 [M][512], W fp16 [N][512].
// BM=64, BN=128, 256 threads (2m x 4n warps, warp tile 32x32).
// 2 buffers x BK=64, consumed in BK=32 halves -> 4 half-stage pipeline.
// 48KB/CTA -> 2 CTAs/SM.
#define BUFSZ 24576
#define SM_A  0
#define SM_B  8192

template <int FINAL>
__global__ __launch_bounds__(256, 2)
void mlp_gemm(const __half* __restrict__ A, const __half* __restrict__ B,
              const float* __restrict__ bias,
              __half* __restrict__ Oh, float* __restrict__ Of32) {
    extern __shared__ __align__(1024) unsigned char sm[];
    const uint32_t smb = smem_u32(sm);
    const int tid = threadIdx.x;
    const int lane = tid & 31, wid = tid >> 5;
    const int wm = wid >> 2, wn = wid & 3;      // 2 x 4 warp grid
    const int m0 = blockIdx.y * 64;
    const int n0 = blockIdx.x * 128;

    float acc[2][4][4];
#pragma unroll
    for (int i = 0; i < 2; i++)
#pragma unroll
        for (int j = 0; j < 4; j++)
#pragma unroll
            for (int q = 0; q < 4; q++) acc[i][j][q] = 0.f;

    // ---- half-stage loader: BK=32 slab (64B per row) into half (ch&1) ------
    const int lr4 = tid >> 2, lc4 = tid & 3;
    auto load_half = [&](int ch) {
        const uint32_t sb = smb + (uint32_t)((ch >> 1) & 1) * BUFSZ;
        const int h4 = (ch & 1) * 4;
        const int k0 = ch * 32;
        {   // A plane: 64 rows x 4 slots (1 cp per thread)
            int r = lr4;
            uint32_t slot = (uint32_t)((h4 + lc4) ^ (r & 7)) << 4;
            CP_ASYNC16(sb + SM_A + r * 128 + slot,
                       A + (size_t)(m0 + r) * 512 + k0 + lc4 * 8);
        }
#pragma unroll
        for (int it = 0; it < 2; it++) {        // B plane: 128 rows x 4 slots
            int r = lr4 + it * 64;
            uint32_t slot = (uint32_t)((h4 + lc4) ^ (r & 7)) << 4;
            CP_ASYNC16(sb + SM_B + r * 128 + slot,
                       B + (size_t)(n0 + r) * 512 + k0 + lc4 * 8);
        }
    };

    const int arow = lane & 15;
    const int kbl  = lane >> 4;

    uint32_t aoff[2], boff[2];
    int amod[2], bmod[2];
#pragma unroll
    for (int mf = 0; mf < 2; mf++) {
        int r = wm * 32 + mf * 16 + arow;       // 0..63
        aoff[mf] = r * 128; amod[mf] = r & 7;
    }
#pragma unroll
    for (int g = 0; g < 2; g++) {
        int r = wn * 32 + g * 16 + arow;        // 0..127
        boff[g] = r * 128; bmod[g] = r & 7;
    }

    load_half(0); CP_COMMIT();
    load_half(1); CP_COMMIT();
    load_half(2); CP_COMMIT();

#pragma unroll 1
    for (int ch = 0; ch < 16; ch++) {
        CP_WAIT2();
        __syncthreads();
        if (ch + 3 < 16) load_half(ch + 3);
        CP_COMMIT();

        const uint32_t sb = smb + (uint32_t)((ch >> 1) & 1) * BUFSZ;
        const int h4 = (ch & 1) * 4;
#pragma unroll
        for (int kk = 0; kk < 2; kk++) {
            const int c = h4 + kk * 2 + kbl;
            uint32_t af[2][4], bf[2][4];
#pragma unroll
            for (int mf = 0; mf < 2; mf++) {
                uint32_t o = aoff[mf] + (uint32_t)((c ^ amod[mf]) << 4);
                ldsm4(af[mf], sb + SM_A + o);
            }
#pragma unroll
            for (int g = 0; g < 2; g++) {
                uint32_t o = boff[g] + (uint32_t)((c ^ bmod[g]) << 4);
                ldsm4(bf[g], sb + SM_B + o);
            }
#pragma unroll
            for (int g = 0; g < 2; g++)
#pragma unroll
                for (int mf = 0; mf < 2; mf++) {
                    mma16816h(acc[mf][2 * g],     af[mf], bf[g][0], bf[g][2]);
                    mma16816h(acc[mf][2 * g + 1], af[mf], bf[g][1], bf[g][3]);
                }
        }
    }

    // ---- epilogue: bias, relu, store ---------------------------------------
    const int OW = FINAL ? DOUT : 512;
    const int qr = lane >> 2, qc = lane & 3;
#pragma unroll
    for (int mf = 0; mf < 2; mf++) {
        const int r0 = m0 + wm * 32 + mf * 16 + qr;
#pragma unroll
        for (int nf = 0; nf < 4; nf++) {
            const int n = n0 + wn * 32 + nf * 8 + qc * 2;
            const float bv0 = bias[n], bv1 = bias[n + 1];
            const float* a = acc[mf][nf];
            float v00 = fmaxf(a[0] + bv0, 0.f);
            float v01 = fmaxf(a[1] + bv1, 0.f);
            float v10 = fmaxf(a[2] + bv0, 0.f);
            float v11 = fmaxf(a[3] + bv1, 0.f);
            if (FINAL) {
                *reinterpret_cast<float2*>(Of32 + (size_t)r0 * OW + n) =
                    make_float2(v00, v01);
                *reinterpret_cast<float2*>(Of32 + (size_t)(r0 + 8) * OW + n) =
                    make_float2(v10, v11);
            } else {
                __half h00 = __float2half_rn(v00), h01 = __float2half_rn(v01);
                __half h10 = __float2half_rn(v10), h11 = __float2half_rn(v11);
                uint32_t p0 = (uint32_t)*reinterpret_cast<unsigned short*>(&h00) |
                              ((uint32_t)*reinterpret_cast<unsigned short*>(&h01) << 16);
                uint32_t p1 = (uint32_t)*reinterpret_cast<unsigned short*>(&h10) |
                              ((uint32_t)*reinterpret_cast<unsigned short*>(&h11) << 16);
                *reinterpret_cast<uint32_t*>(Oh + (size_t)r0 * 512 + n) = p0;
                *reinterpret_cast<uint32_t*>(Oh + (size_t)(r0 + 8) * 512 + n) = p1;
            }
        }
    }
}

// ---------------- tail zero --------------------------------------------------
__global__ void zero_tail(float* out, size_t start, size_t count) {
    size_t i = (size_t)blockIdx.x * blockDim.x + threadIdx.x;
    if (i < count) out[start + i] = 0.0f;
}

// ---------------- launch -----------------------------------------------------
extern "C" void kernel_launch(void* const* d_in, const int* in_sizes, int n_in,
                              void* d_out, int out_size) {
    const float* x     = (const float*)d_in[0];
    const float* W_in  = (const float*)d_in[1];
    const float* b_in  = (const float*)d_in[2];
    const float* W_h   = (const float*)d_in[3];
    const float* b_h   = (const float*)d_in[4];
    const float* W_out = (const float*)d_in[5];
    const float* b_out = (const float*)d_in[6];
    float* out = (float*)d_out;

    __half *actA, *actB, *wi, *wh, *wo;
    cudaGetSymbolAddress((void**)&actA, g_actA);
    cudaGetSymbolAddress((void**)&actB, g_actB);
    cudaGetSymbolAddress((void**)&wi, g_wi);
    cudaGetSymbolAddress((void**)&wh, g_wh);
    cudaGetSymbolAddress((void**)&wo, g_wo);

    const size_t smem = 2 * BUFSZ;  // 48KB per CTA
    cudaFuncSetAttribute(mlp_gemm<0>, cudaFuncAttributeMaxDynamicSharedMemorySize, smem);
    cudaFuncSetAttribute(mlp_gemm<1>, cudaFuncAttributeMaxDynamicSharedMemorySize, smem);

    init_minmax<<<1, DIN>>>();
    colminmax<<<NROWS / 512, DIN>>>(x);
    discretize<<<NROWS / 512, DIN>>>(x);     // -> actA (exact ints in fp16)

    wprep<<<(DIN * NH + 255) / 256, 256>>>(W_in, wi, NH, DIN);
    wprep<<<(NH * NH + 255) / 256, 256>>>(W_h, wh, NH, NH);
    wprep<<<(NH * DOUT + 255) / 256, 256>>>(W_out, wo, DOUT, NH);

    dim3 blk(256);
    dim3 gh(4, NROWS / 64);    // hidden: N=512
    dim3 gf(1, NROWS / 64);    // final:  N=128

    // L1 (exact input)
    mlp_gemm<0><<<gh, blk, smem>>>(actA, wi, b_in, actB, nullptr);
    // L2..L6: shared W_h, ping-pong
    mlp_gemm<0><<<gh, blk, smem>>>(actB, wh, b_h, actA, nullptr);
    mlp_gemm<0><<<gh, blk, smem>>>(actA, wh, b_h, actB, nullptr);
    mlp_gemm<0><<<gh, blk, smem>>>(actB, wh, b_h, actA, nullptr);
    mlp_gemm<0><<<gh, blk, smem>>>(actA, wh, b_h, actB, nullptr);
    mlp_gemm<0><<<gh, blk, smem>>>(actB, wh, b_h, actA, nullptr);
    // L7: final, fp32 out
    mlp_gemm<1><<<gf, blk, smem>>>(actA, wo, b_out, nullptr, out);

    size_t y_elems = (size_t)NROWS * DOUT;
    if ((size_t)out_size > y_elems) {
        size_t cnt = (size_t)out_size - y_elems;
        zero_tail<<<(unsigned)((cnt + 255) / 256), 256>>>(out, y_elems, cnt);
    }
}

// round 15
// speedup vs baseline: 5.1990x; 1.0813x over previous
#include <cuda_runtime.h>
#include <cuda_fp16.h>
#include <cstdint>

#define NROWS 131072
#define DIN   512
#define NH    512
#define DOUT  128
#define NBOUNDS 24

// ---------------- device scratch ---------------------------------------------
__device__ __align__(256) __half g_actA[(size_t)NROWS * 512];
__device__ __align__(256) __half g_actB[(size_t)NROWS * 512];
// weights transposed [N][K], single fp16 plane
__device__ __align__(256) __half g_wi[NH * DIN];
__device__ __align__(256) __half g_wh[NH * NH];
__device__ __align__(256) __half g_wo[DOUT * NH];
__device__ unsigned g_min_enc[DIN];
__device__ unsigned g_max_enc[DIN];

// ---------------- helpers ----------------------------------------------------
__device__ __forceinline__ uint32_t smem_u32(const void* p) {
    uint32_t a;
    asm("{ .reg .u64 t; cvta.to.shared.u64 t, %1; cvt.u32.u64 %0, t; }"
        : "=r"(a) : "l"(p));
    return a;
}
__device__ __forceinline__ void ldsm4(uint32_t* r, uint32_t a) {
    asm volatile("ldmatrix.sync.aligned.m8n8.x4.shared.b16 {%0,%1,%2,%3}, [%4];"
                 : "=r"(r[0]), "=r"(r[1]), "=r"(r[2]), "=r"(r[3]) : "r"(a));
}
__device__ __forceinline__ void mma16816h(float* d, const uint32_t* a,
                                          uint32_t b0, uint32_t b1) {
    asm volatile(
        "mma.sync.aligned.m16n8k16.row.col.f32.f16.f16.f32 "
        "{%0,%1,%2,%3}, {%4,%5,%6,%7}, {%8,%9}, {%0,%1,%2,%3};"
        : "+f"(d[0]), "+f"(d[1]), "+f"(d[2]), "+f"(d[3])
        : "r"(a[0]), "r"(a[1]), "r"(a[2]), "r"(a[3]), "r"(b0), "r"(b1));
}
#define CP_ASYNC16(dst, src) \
    asm volatile("cp.async.cg.shared.global [%0], [%1], 16;" :: "r"(dst), "l"(src))
#define CP_COMMIT() asm volatile("cp.async.commit_group;" ::: "memory")
#define CP_WAIT2()  asm volatile("cp.async.wait_group 2;" ::: "memory")

// ---------------- min/max + discretize ---------------------------------------
__device__ __forceinline__ unsigned enc_f(float f) {
    unsigned u = __float_as_uint(f);
    return (u & 0x80000000u) ? ~u : (u | 0x80000000u);
}
__device__ __forceinline__ float dec_f(unsigned e) {
    unsigned u = (e & 0x80000000u) ? (e & 0x7FFFFFFFu) : ~e;
    return __uint_as_float(u);
}
__global__ void init_minmax() {
    int i = threadIdx.x;
    g_min_enc[i] = 0xFFFFFFFFu;
    g_max_enc[i] = 0x00000000u;
}
__global__ void colminmax(const float* __restrict__ x) {
    const int col = threadIdx.x;
    const size_t base = (size_t)blockIdx.x * 512 * DIN + col;
    float v0 = x[base];
    float mn = v0, mx = v0;
    for (int r = 1; r < 512; r++) {
        float v = x[base + (size_t)r * DIN];
        mn = fminf(mn, v);
        mx = fmaxf(mx, v);
    }
    atomicMin(&g_min_enc[col], enc_f(mn));
    atomicMax(&g_max_enc[col], enc_f(mx));
}
// Windowed bucketize: candidate bin from scaled position, then 6 exact
// boundary compares (covers the <=1.5-bin error of the exact formula).
__global__ void discretize(const float* __restrict__ x) {
    __shared__ float sh_frac[NBOUNDS];
    const int col = threadIdx.x;
    if (col < NBOUNDS) sh_frac[col] = __fdiv_rn((float)(col + 1), 25.0f);
    __syncthreads();
    const float bmin = dec_f(g_min_enc[col]);
    const float bmax = dec_f(g_max_enc[col]);
    const float range = __fsub_rn(bmax, bmin);
    const float s = range > 0.0f ? __fdiv_rn(25.0f, range) : 0.0f;
    const size_t base = (size_t)blockIdx.x * 512 * DIN + col;
    for (int r = 0; r < 512; r++) {
        float v = x[base + (size_t)r * DIN];
        float t = (v - bmin) * s;               // approx bin position, >= 0
        int c = (int)t;
        int b0 = min(max(c - 3, 0), 18);        // window [b0, b0+5] in 0..23
        int idx = b0;
#pragma unroll
        for (int j = 0; j < 6; j++) {
            float bk = __fadd_rn(bmin, __fmul_rn(range, sh_frac[b0 + j]));
            idx += (bk < v) ? 1 : 0;
        }
        g_actA[base + (size_t)r * DIN] = __float2half_rn((float)idx);
    }
}

// ---------------- weight convert + transpose (single fp16 plane) -------------
__global__ void wprep(const float* __restrict__ W, __half* __restrict__ hi,
                      int N, int K) {
    int i = blockIdx.x * blockDim.x + threadIdx.x;
    if (i >= N * K) return;
    int k = i / N, n = i % N;  // W is [K][N]
    hi[(size_t)n * K + k] = __float2half_rn(W[i]);  // transposed [N][K]
}

// ---------------- fp16 GEMM (mma.sync HMMA, fp32 accum) ----------------------
// C = relu(A@W + bias); A fp16 [M][512], W fp16 [N][512].
// BM=64, BN=NFRAG*64, 256 threads (2m x 4n warps, warp tile 32 x NFRAG*16).
// 2 buffers x BK=64, consumed in BK=32 halves -> 4 half-stage pipeline.
// NFRAG=4 (hidden): 80KB/CTA; NFRAG=2 (final): 48KB/CTA. 2 CTAs/SM.
#define SM_A  0
#define SM_B  8192

template <int NFRAG, int FINAL>
__global__ __launch_bounds__(256, 2)
void mlp_gemm(const __half* __restrict__ A, const __half* __restrict__ B,
              const float* __restrict__ bias,
              __half* __restrict__ Oh, float* __restrict__ Of32) {
    constexpr int BUFSZ = (1 + NFRAG) * 8192;
    extern __shared__ __align__(1024) unsigned char sm[];
    const uint32_t smb = smem_u32(sm);
    const int tid = threadIdx.x;
    const int lane = tid & 31, wid = tid >> 5;
    const int wm = wid >> 2, wn = wid & 3;      // 2 x 4 warp grid
    const int m0 = blockIdx.y * 64;
    const int n0 = blockIdx.x * (NFRAG * 64);

    float acc[2][2 * NFRAG][4];
#pragma unroll
    for (int i = 0; i < 2; i++)
#pragma unroll
        for (int j = 0; j < 2 * NFRAG; j++)
#pragma unroll
            for (int q = 0; q < 4; q++) acc[i][j][q] = 0.f;

    // ---- half-stage loader: BK=32 slab (64B per row) into half (ch&1) ------
    const int lr4 = tid >> 2, lc4 = tid & 3;
    auto load_half = [&](int ch) {
        const uint32_t sb = smb + (uint32_t)((ch >> 1) & 1) * BUFSZ;
        const int h4 = (ch & 1) * 4;
        const int k0 = ch * 32;
        {   // A plane: 64 rows x 4 slots (1 cp per thread)
            int r = lr4;
            uint32_t slot = (uint32_t)((h4 + lc4) ^ (r & 7)) << 4;
            CP_ASYNC16(sb + SM_A + r * 128 + slot,
                       A + (size_t)(m0 + r) * 512 + k0 + lc4 * 8);
        }
#pragma unroll
        for (int it = 0; it < NFRAG; it++) {    // B plane: NFRAG*64 rows
            int r = lr4 + it * 64;
            uint32_t slot = (uint32_t)((h4 + lc4) ^ (r & 7)) << 4;
            CP_ASYNC16(sb + SM_B + r * 128 + slot,
                       B + (size_t)(n0 + r) * 512 + k0 + lc4 * 8);
        }
    };

    const int arow = lane & 15;
    const int kbl  = lane >> 4;

    uint32_t aoff[2], boff[NFRAG];
    int amod[2], bmod[NFRAG];
#pragma unroll
    for (int mf = 0; mf < 2; mf++) {
        int r = wm * 32 + mf * 16 + arow;       // 0..63
        aoff[mf] = r * 128; amod[mf] = r & 7;
    }
#pragma unroll
    for (int g = 0; g < NFRAG; g++) {
        int r = wn * (NFRAG * 16) + g * 16 + arow;   // 0..NFRAG*64-1
        boff[g] = r * 128; bmod[g] = r & 7;
    }

    load_half(0); CP_COMMIT();
    load_half(1); CP_COMMIT();
    load_half(2); CP_COMMIT();

#pragma unroll 1
    for (int ch = 0; ch < 16; ch++) {
        CP_WAIT2();
        __syncthreads();
        if (ch + 3 < 16) load_half(ch + 3);
        CP_COMMIT();

        const uint32_t sb = smb + (uint32_t)((ch >> 1) & 1) * BUFSZ;
        const int h4 = (ch & 1) * 4;
#pragma unroll
        for (int kk = 0; kk < 2; kk++) {
            const int c = h4 + kk * 2 + kbl;
            uint32_t af[2][4], bf[NFRAG][4];
#pragma unroll
            for (int mf = 0; mf < 2; mf++) {
                uint32_t o = aoff[mf] + (uint32_t)((c ^ amod[mf]) << 4);
                ldsm4(af[mf], sb + SM_A + o);
            }
#pragma unroll
            for (int g = 0; g < NFRAG; g++) {
                uint32_t o = boff[g] + (uint32_t)((c ^ bmod[g]) << 4);
                ldsm4(bf[g], sb + SM_B + o);
            }
#pragma unroll
            for (int g = 0; g < NFRAG; g++)
#pragma unroll
                for (int mf = 0; mf < 2; mf++) {
                    mma16816h(acc[mf][2 * g],     af[mf], bf[g][0], bf[g][2]);
                    mma16816h(acc[mf][2 * g + 1], af[mf], bf[g][1], bf[g][3]);
                }
        }
    }

    // ---- epilogue: bias, relu, store ---------------------------------------
    const int OW = FINAL ? DOUT : 512;
    const int qr = lane >> 2, qc = lane & 3;
#pragma unroll
    for (int mf = 0; mf < 2; mf++) {
        const int r0 = m0 + wm * 32 + mf * 16 + qr;
#pragma unroll
        for (int nf = 0; nf < 2 * NFRAG; nf++) {
            const int n = n0 + wn * (NFRAG * 16) + nf * 8 + qc * 2;
            const float bv0 = bias[n], bv1 = bias[n + 1];
            const float* a = acc[mf][nf];
            float v00 = fmaxf(a[0] + bv0, 0.f);
            float v01 = fmaxf(a[1] + bv1, 0.f);
            float v10 = fmaxf(a[2] + bv0, 0.f);
            float v11 = fmaxf(a[3] + bv1, 0.f);
            if (FINAL) {
                *reinterpret_cast<float2*>(Of32 + (size_t)r0 * OW + n) =
                    make_float2(v00, v01);
                *reinterpret_cast<float2*>(Of32 + (size_t)(r0 + 8) * OW + n) =
                    make_float2(v10, v11);
            } else {
                __half h00 = __float2half_rn(v00), h01 = __float2half_rn(v01);
                __half h10 = __float2half_rn(v10), h11 = __float2half_rn(v11);
                uint32_t p0 = (uint32_t)*reinterpret_cast<unsigned short*>(&h00) |
                              ((uint32_t)*reinterpret_cast<unsigned short*>(&h01) << 16);
                uint32_t p1 = (uint32_t)*reinterpret_cast<unsigned short*>(&h10) |
                              ((uint32_t)*reinterpret_cast<unsigned short*>(&h11) << 16);
                *reinterpret_cast<uint32_t*>(Oh + (size_t)r0 * 512 + n) = p0;
                *reinterpret_cast<uint32_t*>(Oh + (size_t)(r0 + 8) * 512 + n) = p1;
            }
        }
    }
}

// ---------------- tail zero --------------------------------------------------
__global__ void zero_tail(float* out, size_t start, size_t count) {
    size_t i = (size_t)blockIdx.x * blockDim.x + threadIdx.x;
    if (i < count) out[start + i] = 0.0f;
}

// ---------------- launch -----------------------------------------------------
extern "C" void kernel_launch(void* const* d_in, const int* in_sizes, int n_in,
                              void* d_out, int out_size) {
    const float* x     = (const float*)d_in[0];
    const float* W_in  = (const float*)d_in[1];
    const float* b_in  = (const float*)d_in[2];
    const float* W_h   = (const float*)d_in[3];
    const float* b_h   = (const float*)d_in[4];
    const float* W_out = (const float*)d_in[5];
    const float* b_out = (const float*)d_in[6];
    float* out = (float*)d_out;

    __half *actA, *actB, *wi, *wh, *wo;
    cudaGetSymbolAddress((void**)&actA, g_actA);
    cudaGetSymbolAddress((void**)&actB, g_actB);
    cudaGetSymbolAddress((void**)&wi, g_wi);
    cudaGetSymbolAddress((void**)&wh, g_wh);
    cudaGetSymbolAddress((void**)&wo, g_wo);

    const size_t smemH = 2 * (1 + 4) * 8192;   // 80KB (hidden, NFRAG=4)
    const size_t smemF = 2 * (1 + 2) * 8192;   // 48KB (final, NFRAG=2)
    cudaFuncSetAttribute(mlp_gemm<4, 0>, cudaFuncAttributeMaxDynamicSharedMemorySize, smemH);
    cudaFuncSetAttribute(mlp_gemm<2, 1>, cudaFuncAttributeMaxDynamicSharedMemorySize, smemF);

    // prep (wprep first so ncu -s 5 lands on discretize)
    init_minmax<<<1, DIN>>>();
    wprep<<<(DIN * NH + 255) / 256, 256>>>(W_in, wi, NH, DIN);
    wprep<<<(NH * NH + 255) / 256, 256>>>(W_h, wh, NH, NH);
    wprep<<<(NH * DOUT + 255) / 256, 256>>>(W_out, wo, DOUT, NH);
    colminmax<<<NROWS / 512, DIN>>>(x);
    discretize<<<NROWS / 512, DIN>>>(x);     // -> actA (exact ints in fp16)

    dim3 blk(256);
    dim3 gh(2, NROWS / 64);    // hidden: N=512 -> 2 n-tiles of 256
    dim3 gf(1, NROWS / 64);    // final:  N=128 -> 1 n-tile of 128

    // L1 (exact input)
    mlp_gemm<4, 0><<<gh, blk, smemH>>>(actA, wi, b_in, actB, nullptr);
    // L2..L6: shared W_h, ping-pong
    mlp_gemm<4, 0><<<gh, blk, smemH>>>(actB, wh, b_h, actA, nullptr);
    mlp_gemm<4, 0><<<gh, blk, smemH>>>(actA, wh, b_h, actB, nullptr);
    mlp_gemm<4, 0><<<gh, blk, smemH>>>(actB, wh, b_h, actA, nullptr);
    mlp_gemm<4, 0><<<gh, blk, smemH>>>(actA, wh, b_h, actB, nullptr);
    mlp_gemm<4, 0><<<gh, blk, smemH>>>(actB, wh, b_h, actA, nullptr);
    // L7: final, fp32 out
    mlp_gemm<2, 1><<<gf, blk, smemF>>>(actA, wo, b_out, nullptr, out);

    size_t y_elems = (size_t)NROWS * DOUT;
    if ((size_t)out_size > y_elems) {
        size_t cnt = (size_t)out_size - y_elems;
        zero_tail<<<(unsigned)((cnt + 255) / 256), 256>>>(out, y_elems, cnt);
    }
}